// round 4
// baseline (speedup 1.0000x reference)
#include <cuda_runtime.h>

#define N_NODES   100000
#define N_EDGES   1600000
#define N_FEAT    128
#define N_WORKERS 4

// Scratch: degree counters + inverse-sqrt degrees + index-width flag.
__device__ unsigned int g_deg[2 * N_WORKERS * N_NODES];   // [out | in] per worker
__device__ float        g_dinv[2 * N_WORKERS * N_NODES];  // [out | in] per worker
__device__ int          g_is64;

// ---------------------------------------------------------------------------
// Detect whether indices are int64 or int32. Indices are in [0, 100000), so
// for int64 every odd 32-bit word is 0. For random int32 data, 256 odd words
// all being zero has probability ~(1e-5)^256 == never.
// ---------------------------------------------------------------------------
__global__ void detect_idx_kernel(const unsigned int* __restrict__ p) {
    __shared__ int any;
    if (threadIdx.x == 0) any = 0;
    __syncthreads();
    if (p[2 * threadIdx.x + 1] != 0u) any = 1;
    __syncthreads();
    if (threadIdx.x == 0) g_is64 = (any == 0) ? 1 : 0;
}

__device__ __forceinline__ int load_idx(const void* p, long long i, int is64) {
    if (is64) return (int)((const long long*)p)[i];
    return ((const int*)p)[i];
}

// ---------------------------------------------------------------------------
// Degree counting: all workers in one launch (grid.y = worker).
// ---------------------------------------------------------------------------
__global__ void degree_kernel(const void* __restrict__ src, const void* __restrict__ dst) {
    int is64 = g_is64;
    int w = blockIdx.y;
    long long base = (long long)w * N_EDGES;
    for (int e = blockIdx.x * blockDim.x + threadIdx.x; e < N_EDGES;
         e += gridDim.x * blockDim.x) {
        int s = load_idx(src, base + e, is64);
        int d = load_idx(dst, base + e, is64);
        atomicAdd(&g_deg[w * N_NODES + s], 1u);
        atomicAdd(&g_deg[N_WORKERS * N_NODES + w * N_NODES + d], 1u);
    }
}

__global__ void dinv_kernel() {
    int i = blockIdx.x * blockDim.x + threadIdx.x;
    if (i < 2 * N_WORKERS * N_NODES) {
        float c = (float)g_deg[i];
        g_dinv[i] = rsqrtf(fmaxf(c, 1.0f));
    }
}

// ---------------------------------------------------------------------------
// Scatter-add: one warp per edge. Lane l handles feats [4l, 4l+4).
// out[dst] += feat[src] * out_deg(src)^-1/2 via 16B vector atomic.
// One worker per launch so the 51.2MB agg working set stays L2-resident.
// ---------------------------------------------------------------------------
__global__ void __launch_bounds__(256)
scatter_kernel(const float* __restrict__ feat,
               const void* __restrict__ src,
               const void* __restrict__ dst,
               float* __restrict__ out, int w) {
    int is64 = g_is64;
    int lane = threadIdx.x & 31;
    long long e = (long long)((blockIdx.x * blockDim.x + threadIdx.x) >> 5);
    if (e >= N_EDGES) return;
    long long base = (long long)w * N_EDGES;
    int s = load_idx(src, base + e, is64);
    int d = load_idx(dst, base + e, is64);
    float sc = g_dinv[w * N_NODES + s];

    const float4* fp = (const float4*)(feat + ((long long)w * N_NODES + s) * N_FEAT) + lane;
    float4 v = *fp;
    v.x *= sc; v.y *= sc; v.z *= sc; v.w *= sc;

    float* op = out + ((long long)w * N_NODES + d) * N_FEAT + lane * 4;
    asm volatile("red.global.add.v4.f32 [%0], {%1,%2,%3,%4};"
                 :: "l"(op), "f"(v.x), "f"(v.y), "f"(v.z), "f"(v.w) : "memory");
}

// ---------------------------------------------------------------------------
// Epilogue GEMM, in place on d_out:
//   out_row = (agg_row * in_deg^-1/2) @ W + bias
// Block: 256 threads, 64-node tile. W (64KB) + scaled agg tile (32KB) in smem.
// Thread (tx, ty): tx in [0,32) owns 4 hidden cols, ty in [0,8) owns 8 nodes.
// agg smem reads broadcast across the warp; W reads are conflict-free LDS.128.
// ---------------------------------------------------------------------------
__global__ void __launch_bounds__(256)
gemm_kernel(const float* __restrict__ weight,
            const float* __restrict__ bias,
            float* __restrict__ out) {
    extern __shared__ float sm[];
    float* Ws = sm;                    // 128*128
    float* As = sm + N_FEAT * N_FEAT;  // 64*128
    int t = threadIdx.x;

    // Load W
    for (int i = t; i < (N_FEAT * N_FEAT) / 4; i += 256)
        ((float4*)Ws)[i] = ((const float4*)weight)[i];

    long long r0 = (long long)blockIdx.x * 64;

    // Load 64 agg rows, fusing the in-degree scaling
    for (int i = t; i < (64 * N_FEAT) / 4; i += 256) {
        int row = i >> 5;  // 32 float4 per row
        float sc = g_dinv[N_WORKERS * N_NODES + r0 + row];
        float4 v = ((const float4*)(out + r0 * N_FEAT))[i];
        v.x *= sc; v.y *= sc; v.z *= sc; v.w *= sc;
        ((float4*)As)[i] = v;
    }
    __syncthreads();

    int tx = t & 31;
    int ty = t >> 5;
    float acc[8][4];
#pragma unroll
    for (int k = 0; k < 8; k++)
#pragma unroll
        for (int j = 0; j < 4; j++) acc[k][j] = 0.0f;

#pragma unroll 4
    for (int f = 0; f < N_FEAT; f++) {
        float4 wv = *(const float4*)&Ws[f * N_FEAT + tx * 4];
#pragma unroll
        for (int k = 0; k < 8; k++) {
            float a = As[(ty * 8 + k) * N_FEAT + f];
            acc[k][0] += a * wv.x;
            acc[k][1] += a * wv.y;
            acc[k][2] += a * wv.z;
            acc[k][3] += a * wv.w;
        }
    }

    float4 bv = *(const float4*)&bias[tx * 4];
#pragma unroll
    for (int k = 0; k < 8; k++) {
        long long row = r0 + ty * 8 + k;
        float4 o;
        o.x = acc[k][0] + bv.x;
        o.y = acc[k][1] + bv.y;
        o.z = acc[k][2] + bv.z;
        o.w = acc[k][3] + bv.w;
        *(float4*)(out + row * N_FEAT + tx * 4) = o;
    }
}

// ---------------------------------------------------------------------------
extern "C" void kernel_launch(void* const* d_in, const int* in_sizes, int n_in,
                              void* d_out, int out_size) {
    const float* feats  = (const float*)d_in[0];
    const float* weight = (const float*)d_in[1];
    const float* bias   = (const float*)d_in[2];
    const void*  src    = d_in[3];
    const void*  dst    = d_in[4];
    float* out = (float*)d_out;

    void* degp = nullptr;
    cudaGetSymbolAddress(&degp, g_deg);
    cudaMemsetAsync(degp, 0, sizeof(unsigned int) * 2 * N_WORKERS * N_NODES);
    cudaMemsetAsync(d_out, 0, (size_t)out_size * sizeof(float));

    detect_idx_kernel<<<1, 256>>>((const unsigned int*)src);

    dim3 dgrid(2048, N_WORKERS);
    degree_kernel<<<dgrid, 256>>>(src, dst);
    dinv_kernel<<<(2 * N_WORKERS * N_NODES + 255) / 256, 256>>>();

    // One warp per edge; serialize workers to keep per-worker agg in L2.
    int sblocks = (N_EDGES * 32) / 256;  // 200000
    for (int w = 0; w < N_WORKERS; w++)
        scatter_kernel<<<sblocks, 256>>>(feats, src, dst, out, w);

    cudaFuncSetAttribute(gemm_kernel, cudaFuncAttributeMaxDynamicSharedMemorySize,
                         (N_FEAT * N_FEAT + 64 * N_FEAT) * sizeof(float));
    gemm_kernel<<<(N_WORKERS * N_NODES) / 64, 256,
                  (N_FEAT * N_FEAT + 64 * N_FEAT) * sizeof(float)>>>(weight, bias, out);
}

// round 5
// speedup vs baseline: 1.9045x; 1.9045x over previous
#include <cuda_runtime.h>

#define N_NODES   100000
#define N_EDGES   1600000
#define N_FEAT    128
#define N_WORKERS 4
#define SCAN_B    1024
#define N_SBLK    ((N_NODES + SCAN_B - 1) / SCAN_B)   // 98

// Scratch (static device arrays; no allocation).
__device__ unsigned g_deg [2 * N_WORKERS * N_NODES];  // [out | in] raw counts
__device__ float    g_dinv[2 * N_WORKERS * N_NODES];  // [out | in] deg^-1/2 (clipped)
__device__ int      g_is64;
__device__ unsigned g_off [N_WORKERS * N_NODES];      // CSR row offsets (by dst)
__device__ unsigned g_cur [N_WORKERS * N_NODES];      // fill cursors
__device__ unsigned g_bsum[N_WORKERS * N_SBLK];       // scan block sums
__device__ int      g_csr [N_WORKERS * N_EDGES];      // src ids grouped by dst

// ---------------------------------------------------------------------------
// int64 vs int32 index detection (indices < 100000 -> odd words zero iff i64).
// ---------------------------------------------------------------------------
__global__ void detect_idx_kernel(const unsigned int* __restrict__ p) {
    __shared__ int any;
    if (threadIdx.x == 0) any = 0;
    __syncthreads();
    if (p[2 * threadIdx.x + 1] != 0u) any = 1;
    __syncthreads();
    if (threadIdx.x == 0) g_is64 = (any == 0) ? 1 : 0;
}

__device__ __forceinline__ int load_idx(const void* p, long long i, int is64) {
    if (is64) return (int)((const long long*)p)[i];
    return ((const int*)p)[i];
}

// ---------------------------------------------------------------------------
// Degree counting (all workers, grid.y = worker).
// ---------------------------------------------------------------------------
__global__ void degree_kernel(const void* __restrict__ src, const void* __restrict__ dst) {
    int is64 = g_is64;
    int w = blockIdx.y;
    long long base = (long long)w * N_EDGES;
    for (int e = blockIdx.x * blockDim.x + threadIdx.x; e < N_EDGES;
         e += gridDim.x * blockDim.x) {
        int s = load_idx(src, base + e, is64);
        int d = load_idx(dst, base + e, is64);
        atomicAdd(&g_deg[w * N_NODES + s], 1u);
        atomicAdd(&g_deg[N_WORKERS * N_NODES + w * N_NODES + d], 1u);
    }
}

__global__ void dinv_kernel() {
    int i = blockIdx.x * blockDim.x + threadIdx.x;
    if (i < 2 * N_WORKERS * N_NODES) {
        float c = (float)g_deg[i];
        g_dinv[i] = rsqrtf(fmaxf(c, 1.0f));
    }
}

// ---------------------------------------------------------------------------
// Exclusive scan of in-degrees -> CSR offsets (3 small kernels).
// ---------------------------------------------------------------------------
__global__ void scan1_kernel() {
    __shared__ unsigned s[SCAN_B];
    int w = blockIdx.y;
    int i = blockIdx.x * SCAN_B + threadIdx.x;
    unsigned v = (i < N_NODES) ? g_deg[N_WORKERS * N_NODES + w * N_NODES + i] : 0u;
    s[threadIdx.x] = v;
    __syncthreads();
    for (int d = 1; d < SCAN_B; d <<= 1) {
        unsigned t = (threadIdx.x >= d) ? s[threadIdx.x - d] : 0u;
        __syncthreads();
        s[threadIdx.x] += t;
        __syncthreads();
    }
    if (i < N_NODES) g_off[w * N_NODES + i] = s[threadIdx.x] - v;  // exclusive
    if (threadIdx.x == SCAN_B - 1) g_bsum[w * N_SBLK + blockIdx.x] = s[threadIdx.x];
}

__global__ void scan2_kernel() {
    int w = blockIdx.x;
    if (threadIdx.x != 0) return;
    unsigned acc = 0;
    for (int b = 0; b < N_SBLK; b++) {
        unsigned t = g_bsum[w * N_SBLK + b];
        g_bsum[w * N_SBLK + b] = acc;
        acc += t;
    }
}

__global__ void scan3_kernel() {
    int w = blockIdx.y;
    int i = blockIdx.x * 256 + threadIdx.x;
    if (i < N_NODES) g_off[w * N_NODES + i] += g_bsum[w * N_SBLK + i / SCAN_B];
}

// ---------------------------------------------------------------------------
// CSR fill: bucket src ids by dst. Small 4B atomics only.
// ---------------------------------------------------------------------------
__global__ void fill_kernel(const void* __restrict__ src, const void* __restrict__ dst) {
    int is64 = g_is64;
    int w = blockIdx.y;
    long long base = (long long)w * N_EDGES;
    for (int e = blockIdx.x * blockDim.x + threadIdx.x; e < N_EDGES;
         e += gridDim.x * blockDim.x) {
        int s = load_idx(src, base + e, is64);
        int d = load_idx(dst, base + e, is64);
        unsigned pos = g_off[w * N_NODES + d] + atomicAdd(&g_cur[w * N_NODES + d], 1u);
        g_csr[base + pos] = s;
    }
}

// ---------------------------------------------------------------------------
// Fused gather + scale + GEMM + bias. One launch per worker (L2 residency).
// Block = 256 threads, 64-node tile.
//   Phase 1: W -> smem (64 KB)
//   Phase 2: each warp gathers 8 nodes' aggregated rows into regs -> smem As
//   Phase 3: register-tiled GEMM (8 nodes x 4 cols / thread), f unrolled x4
// ---------------------------------------------------------------------------
__global__ void __launch_bounds__(256)
fused_kernel(const float* __restrict__ feat,
             const float* __restrict__ weight,
             const float* __restrict__ bias,
             float* __restrict__ out, int w) {
    extern __shared__ float sm[];
    float* Ws = sm;                    // 128*128
    float* As = sm + N_FEAT * N_FEAT;  // 64*128
    int t = threadIdx.x;
    int lane = t & 31;
    int warp = t >> 5;

    for (int i = t; i < (N_FEAT * N_FEAT) / 4; i += 256)
        ((float4*)Ws)[i] = ((const float4*)weight)[i];

    int n0 = blockIdx.x * 64;
    const float* featw    = feat + (long long)w * N_NODES * N_FEAT;
    const int*   csrw     = g_csr + (long long)w * N_EDGES;
    const float* dinv_out = g_dinv + w * N_NODES;
    const float* dinv_in  = g_dinv + N_WORKERS * N_NODES + w * N_NODES;
    const unsigned* offw  = g_off + w * N_NODES;
    const unsigned* degw  = g_deg + N_WORKERS * N_NODES + w * N_NODES;

    // Phase 2: gather. Warp g handles nodes n0+g*8 .. n0+g*8+7.
#pragma unroll
    for (int i = 0; i < 8; i++) {
        int node = n0 + warp * 8 + i;
        float4 acc = make_float4(0.f, 0.f, 0.f, 0.f);
        if (node < N_NODES) {
            unsigned st  = offw[node];
            unsigned deg = degw[node];
            const int* ep = csrw + st;
#pragma unroll 4
            for (unsigned j = 0; j < deg; j++) {
                int s = ep[j];
                float sc = dinv_out[s];
                float4 f = *((const float4*)(featw + (long long)s * N_FEAT) + lane);
                acc.x += f.x * sc; acc.y += f.y * sc;
                acc.z += f.z * sc; acc.w += f.w * sc;
            }
            float si = dinv_in[node];
            acc.x *= si; acc.y *= si; acc.z *= si; acc.w *= si;
        }
        *(float4*)&As[(warp * 8 + i) * N_FEAT + lane * 4] = acc;
    }
    __syncthreads();

    // Phase 3: GEMM. Thread (tx,ty): cols [4tx,4tx+4), rows ty*8..ty*8+7.
    int tx = t & 31;
    int ty = t >> 5;
    float acc[8][4];
#pragma unroll
    for (int k = 0; k < 8; k++)
#pragma unroll
        for (int j = 0; j < 4; j++) acc[k][j] = 0.0f;

    for (int f = 0; f < N_FEAT; f += 4) {
        float4 wv0 = *(const float4*)&Ws[(f + 0) * N_FEAT + tx * 4];
        float4 wv1 = *(const float4*)&Ws[(f + 1) * N_FEAT + tx * 4];
        float4 wv2 = *(const float4*)&Ws[(f + 2) * N_FEAT + tx * 4];
        float4 wv3 = *(const float4*)&Ws[(f + 3) * N_FEAT + tx * 4];
#pragma unroll
        for (int k = 0; k < 8; k++) {
            float4 a = *(const float4*)&As[(ty * 8 + k) * N_FEAT + f];
            acc[k][0] += a.x * wv0.x; acc[k][1] += a.x * wv0.y;
            acc[k][2] += a.x * wv0.z; acc[k][3] += a.x * wv0.w;
            acc[k][0] += a.y * wv1.x; acc[k][1] += a.y * wv1.y;
            acc[k][2] += a.y * wv1.z; acc[k][3] += a.y * wv1.w;
            acc[k][0] += a.z * wv2.x; acc[k][1] += a.z * wv2.y;
            acc[k][2] += a.z * wv2.z; acc[k][3] += a.z * wv2.w;
            acc[k][0] += a.w * wv3.x; acc[k][1] += a.w * wv3.y;
            acc[k][2] += a.w * wv3.z; acc[k][3] += a.w * wv3.w;
        }
    }

    float4 bv = *(const float4*)&bias[tx * 4];
    float* outw = out + (long long)w * N_NODES * N_FEAT;
#pragma unroll
    for (int k = 0; k < 8; k++) {
        int row = n0 + ty * 8 + k;
        if (row < N_NODES) {
            float4 o;
            o.x = acc[k][0] + bv.x;
            o.y = acc[k][1] + bv.y;
            o.z = acc[k][2] + bv.z;
            o.w = acc[k][3] + bv.w;
            *(float4*)(outw + (long long)row * N_FEAT + tx * 4) = o;
        }
    }
}

// ---------------------------------------------------------------------------
extern "C" void kernel_launch(void* const* d_in, const int* in_sizes, int n_in,
                              void* d_out, int out_size) {
    const float* feats  = (const float*)d_in[0];
    const float* weight = (const float*)d_in[1];
    const float* bias   = (const float*)d_in[2];
    const void*  src    = d_in[3];
    const void*  dst    = d_in[4];
    float* out = (float*)d_out;

    void* p = nullptr;
    cudaGetSymbolAddress(&p, g_deg);
    cudaMemsetAsync(p, 0, sizeof(unsigned) * 2 * N_WORKERS * N_NODES);
    cudaGetSymbolAddress(&p, g_cur);
    cudaMemsetAsync(p, 0, sizeof(unsigned) * N_WORKERS * N_NODES);

    detect_idx_kernel<<<1, 256>>>((const unsigned int*)src);

    dim3 dgrid(2048, N_WORKERS);
    degree_kernel<<<dgrid, 256>>>(src, dst);
    dinv_kernel<<<(2 * N_WORKERS * N_NODES + 255) / 256, 256>>>();

    dim3 sgrid1(N_SBLK, N_WORKERS);
    scan1_kernel<<<sgrid1, SCAN_B>>>();
    scan2_kernel<<<N_WORKERS, 32>>>();
    dim3 sgrid3((N_NODES + 255) / 256, N_WORKERS);
    scan3_kernel<<<sgrid3, 256>>>();

    fill_kernel<<<dgrid, 256>>>(src, dst);

    const int smem = (N_FEAT * N_FEAT + 64 * N_FEAT) * sizeof(float);  // 96 KB
    cudaFuncSetAttribute(fused_kernel, cudaFuncAttributeMaxDynamicSharedMemorySize, smem);
    int fblocks = (N_NODES + 63) / 64;  // 1563
    for (int w = 0; w < N_WORKERS; w++)
        fused_kernel<<<fblocks, 256, smem>>>(feats, weight, bias, out, w);
}

// round 6
// speedup vs baseline: 2.0621x; 1.0827x over previous
#include <cuda_runtime.h>

#define N_NODES   100000
#define N_EDGES   1600000
#define N_FEAT    128
#define N_WORKERS 4
#define SCAN_B    1024
#define N_SBLK    ((N_NODES + SCAN_B - 1) / SCAN_B)   // 98

typedef unsigned long long u64;

// Scratch (static device arrays; no allocation).
__device__ unsigned g_deg [2 * N_WORKERS * N_NODES];  // [out | in] raw counts
__device__ float    g_dinv[2 * N_WORKERS * N_NODES];  // [out | in] deg^-1/2 (clipped)
__device__ int      g_is64;
__device__ unsigned g_off [N_WORKERS * N_NODES];      // CSR row offsets (by dst)
__device__ unsigned g_cur [N_WORKERS * N_NODES];      // fill cursors
__device__ unsigned g_bsum[N_WORKERS * N_SBLK];       // scan block sums
__device__ int2     g_csr [N_WORKERS * N_EDGES];      // (src, outdeg^-1/2) by dst

// Packed fp32x2 FMA (Blackwell FFMA2; ptxas never emits this from C++).
#define FMA2(acc, a, b) \
    asm("fma.rn.f32x2 %0, %1, %2, %0;" : "+l"(acc) : "l"(a), "l"(b))

// ---------------------------------------------------------------------------
// int64 vs int32 index detection (indices < 100000 -> odd words zero iff i64).
// ---------------------------------------------------------------------------
__global__ void detect_idx_kernel(const unsigned int* __restrict__ p) {
    __shared__ int any;
    if (threadIdx.x == 0) any = 0;
    __syncthreads();
    if (p[2 * threadIdx.x + 1] != 0u) any = 1;
    __syncthreads();
    if (threadIdx.x == 0) g_is64 = (any == 0) ? 1 : 0;
}

__device__ __forceinline__ int load_idx(const void* p, long long i, int is64) {
    if (is64) return (int)((const long long*)p)[i];
    return ((const int*)p)[i];
}

// ---------------------------------------------------------------------------
// Degree counting (all workers, grid.y = worker).
// ---------------------------------------------------------------------------
__global__ void degree_kernel(const void* __restrict__ src, const void* __restrict__ dst) {
    int is64 = g_is64;
    int w = blockIdx.y;
    long long base = (long long)w * N_EDGES;
    for (int e = blockIdx.x * blockDim.x + threadIdx.x; e < N_EDGES;
         e += gridDim.x * blockDim.x) {
        int s = load_idx(src, base + e, is64);
        int d = load_idx(dst, base + e, is64);
        atomicAdd(&g_deg[w * N_NODES + s], 1u);
        atomicAdd(&g_deg[N_WORKERS * N_NODES + w * N_NODES + d], 1u);
    }
}

__global__ void dinv_kernel() {
    int i = blockIdx.x * blockDim.x + threadIdx.x;
    if (i < 2 * N_WORKERS * N_NODES) {
        float c = (float)g_deg[i];
        g_dinv[i] = rsqrtf(fmaxf(c, 1.0f));
    }
}

// ---------------------------------------------------------------------------
// Exclusive scan of in-degrees -> CSR offsets.
// ---------------------------------------------------------------------------
__global__ void scan1_kernel() {
    __shared__ unsigned s[SCAN_B];
    int w = blockIdx.y;
    int i = blockIdx.x * SCAN_B + threadIdx.x;
    unsigned v = (i < N_NODES) ? g_deg[N_WORKERS * N_NODES + w * N_NODES + i] : 0u;
    s[threadIdx.x] = v;
    __syncthreads();
    for (int d = 1; d < SCAN_B; d <<= 1) {
        unsigned t = (threadIdx.x >= d) ? s[threadIdx.x - d] : 0u;
        __syncthreads();
        s[threadIdx.x] += t;
        __syncthreads();
    }
    if (i < N_NODES) g_off[w * N_NODES + i] = s[threadIdx.x] - v;  // exclusive
    if (threadIdx.x == SCAN_B - 1) g_bsum[w * N_SBLK + blockIdx.x] = s[threadIdx.x];
}

__global__ void scan2_kernel() {
    int w = blockIdx.x;
    if (threadIdx.x != 0) return;
    unsigned acc = 0;
    for (int b = 0; b < N_SBLK; b++) {
        unsigned t = g_bsum[w * N_SBLK + b];
        g_bsum[w * N_SBLK + b] = acc;
        acc += t;
    }
}

__global__ void scan3_kernel() {
    int w = blockIdx.y;
    int i = blockIdx.x * 256 + threadIdx.x;
    if (i < N_NODES) g_off[w * N_NODES + i] += g_bsum[w * N_SBLK + i / SCAN_B];
}

// ---------------------------------------------------------------------------
// CSR fill: bucket (src, outdeg^-1/2) by dst. Small 4B atomics only.
// ---------------------------------------------------------------------------
__global__ void fill_kernel(const void* __restrict__ src, const void* __restrict__ dst) {
    int is64 = g_is64;
    int w = blockIdx.y;
    long long base = (long long)w * N_EDGES;
    for (int e = blockIdx.x * blockDim.x + threadIdx.x; e < N_EDGES;
         e += gridDim.x * blockDim.x) {
        int s = load_idx(src, base + e, is64);
        int d = load_idx(dst, base + e, is64);
        unsigned pos = g_off[w * N_NODES + d] + atomicAdd(&g_cur[w * N_NODES + d], 1u);
        g_csr[base + pos] = make_int2(s, __float_as_int(g_dinv[w * N_NODES + s]));
    }
}

// ---------------------------------------------------------------------------
// Fused gather + scale + FFMA2 GEMM + bias. One launch, grid (1563, 4).
// blockIdx linearization keeps each worker's feat slab L2-resident in turn.
//   Phase 1: W -> smem, INTERLEAVED as (W[2f][c], W[2f+1][c]) f32-pairs
//   Phase 2: each warp gathers 8 nodes' aggregated rows -> smem As
//   Phase 3: even/odd-split register-tiled GEMM on fma.rn.f32x2
// ---------------------------------------------------------------------------
__global__ void __launch_bounds__(256)
fused_kernel(const float* __restrict__ feat,
             const float* __restrict__ weight,
             const float* __restrict__ bias,
             float* __restrict__ out) {
    extern __shared__ float sm[];
    float* Wi = sm;                    // 128*128 (interleaved f-pairs)
    float* As = sm + N_FEAT * N_FEAT;  // 64*128
    u64* Wu = (u64*)Wi;
    int t = threadIdx.x;
    int lane = t & 31;
    int warp = t >> 5;
    int w = blockIdx.y;

    // Phase 1: Wu[fp*128 + c] = (W[2fp][c], W[2fp+1][c])
    for (int i = t; i < (N_FEAT / 2) * N_FEAT; i += 256) {
        int fp = i >> 7;
        int c  = i & 127;
        float w0 = weight[(2 * fp)     * N_FEAT + c];
        float w1 = weight[(2 * fp + 1) * N_FEAT + c];
        u64 pk;
        asm("mov.b64 %0, {%1, %2};" : "=l"(pk) : "f"(w0), "f"(w1));
        Wu[i] = pk;
    }

    int n0 = blockIdx.x * 64;
    const float*    featw   = feat + (long long)w * N_NODES * N_FEAT;
    const int2*     csrw    = g_csr + (long long)w * N_EDGES;
    const float*    dinv_in = g_dinv + N_WORKERS * N_NODES + w * N_NODES;
    const unsigned* offw    = g_off + w * N_NODES;
    const unsigned* degw    = g_deg + N_WORKERS * N_NODES + w * N_NODES;

    // Phase 2: gather. Warp g handles nodes n0+g*8 .. n0+g*8+7.
#pragma unroll
    for (int i = 0; i < 8; i++) {
        int node = n0 + warp * 8 + i;
        float4 acc = make_float4(0.f, 0.f, 0.f, 0.f);
        if (node < N_NODES) {
            unsigned st  = offw[node];
            unsigned deg = degw[node];
            const int2* ep = csrw + st;
#pragma unroll 8
            for (unsigned j = 0; j < deg; j++) {
                int2 e = ep[j];                 // broadcast 8B
                float sc = __int_as_float(e.y);
                float4 f = *((const float4*)(featw + (long long)e.x * N_FEAT) + lane);
                acc.x += f.x * sc; acc.y += f.y * sc;
                acc.z += f.z * sc; acc.w += f.w * sc;
            }
            float si = dinv_in[node];
            acc.x *= si; acc.y *= si; acc.z *= si; acc.w *= si;
        }
        *(float4*)&As[(warp * 8 + i) * N_FEAT + lane * 4] = acc;
    }
    __syncthreads();

    // Phase 3: GEMM. tx in [0,32): cols {2tx,2tx+1,64+2tx,64+2tx+1};
    //          ty in [0,8): rows ty*8 .. ty*8+7. Even/odd K split in f32x2.
    int tx = t & 31;
    int ty = t >> 5;
    u64 acc[8][4];
#pragma unroll
    for (int k = 0; k < 8; k++)
#pragma unroll
        for (int j = 0; j < 4; j++) acc[k][j] = 0ull;

    for (int fp = 0; fp < N_FEAT / 2; fp += 2) {
        // W pairs for fpairs fp and fp+1 (warp-contiguous LDS.128, no conflicts)
        ulonglong2 w0a = *(const ulonglong2*)&Wu[fp * 128 + 2 * tx];
        ulonglong2 w0b = *(const ulonglong2*)&Wu[fp * 128 + 64 + 2 * tx];
        ulonglong2 w1a = *(const ulonglong2*)&Wu[(fp + 1) * 128 + 2 * tx];
        ulonglong2 w1b = *(const ulonglong2*)&Wu[(fp + 1) * 128 + 64 + 2 * tx];
#pragma unroll
        for (int k = 0; k < 8; k++) {
            // a.x = (A[2fp], A[2fp+1]), a.y = (A[2fp+2], A[2fp+3]) — broadcast
            ulonglong2 a = *(const ulonglong2*)&As[(ty * 8 + k) * N_FEAT + 2 * fp];
            FMA2(acc[k][0], a.x, w0a.x);
            FMA2(acc[k][1], a.x, w0a.y);
            FMA2(acc[k][2], a.x, w0b.x);
            FMA2(acc[k][3], a.x, w0b.y);
            FMA2(acc[k][0], a.y, w1a.x);
            FMA2(acc[k][1], a.y, w1a.y);
            FMA2(acc[k][2], a.y, w1b.x);
            FMA2(acc[k][3], a.y, w1b.y);
        }
    }

    float2 bA = *(const float2*)&bias[2 * tx];
    float2 bB = *(const float2*)&bias[64 + 2 * tx];
    float* outw = out + (long long)w * N_NODES * N_FEAT;
#pragma unroll
    for (int k = 0; k < 8; k++) {
        int row = n0 + ty * 8 + k;
        if (row < N_NODES) {
            float lo, hi;
            float2 rA, rB;
            asm("mov.b64 {%0, %1}, %2;" : "=f"(lo), "=f"(hi) : "l"(acc[k][0]));
            rA.x = lo + hi + bA.x;
            asm("mov.b64 {%0, %1}, %2;" : "=f"(lo), "=f"(hi) : "l"(acc[k][1]));
            rA.y = lo + hi + bA.y;
            asm("mov.b64 {%0, %1}, %2;" : "=f"(lo), "=f"(hi) : "l"(acc[k][2]));
            rB.x = lo + hi + bB.x;
            asm("mov.b64 {%0, %1}, %2;" : "=f"(lo), "=f"(hi) : "l"(acc[k][3]));
            rB.y = lo + hi + bB.y;
            *(float2*)(outw + (long long)row * N_FEAT + 2 * tx)      = rA;
            *(float2*)(outw + (long long)row * N_FEAT + 64 + 2 * tx) = rB;
        }
    }
}

// ---------------------------------------------------------------------------
extern "C" void kernel_launch(void* const* d_in, const int* in_sizes, int n_in,
                              void* d_out, int out_size) {
    const float* feats  = (const float*)d_in[0];
    const float* weight = (const float*)d_in[1];
    const float* bias   = (const float*)d_in[2];
    const void*  src    = d_in[3];
    const void*  dst    = d_in[4];
    float* out = (float*)d_out;

    void* p = nullptr;
    cudaGetSymbolAddress(&p, g_deg);
    cudaMemsetAsync(p, 0, sizeof(unsigned) * 2 * N_WORKERS * N_NODES);
    cudaGetSymbolAddress(&p, g_cur);
    cudaMemsetAsync(p, 0, sizeof(unsigned) * N_WORKERS * N_NODES);

    detect_idx_kernel<<<1, 256>>>((const unsigned int*)src);

    dim3 dgrid(2048, N_WORKERS);
    degree_kernel<<<dgrid, 256>>>(src, dst);
    dinv_kernel<<<(2 * N_WORKERS * N_NODES + 255) / 256, 256>>>();

    dim3 sgrid1(N_SBLK, N_WORKERS);
    scan1_kernel<<<sgrid1, SCAN_B>>>();
    scan2_kernel<<<N_WORKERS, 32>>>();
    dim3 sgrid3((N_NODES + 255) / 256, N_WORKERS);
    scan3_kernel<<<sgrid3, 256>>>();

    fill_kernel<<<dgrid, 256>>>(src, dst);

    const int smem = (N_FEAT * N_FEAT + 64 * N_FEAT) * sizeof(float);  // 96 KB
    cudaFuncSetAttribute(fused_kernel, cudaFuncAttributeMaxDynamicSharedMemorySize, smem);
    dim3 fgrid((N_NODES + 63) / 64, N_WORKERS);  // (1563, 4)
    fused_kernel<<<fgrid, 256, smem>>>(feats, weight, bias, out);
}

// round 8
// speedup vs baseline: 2.1072x; 1.0219x over previous
#include <cuda_runtime.h>
#include <cuda_fp16.h>

#define N_NODES   100000
#define N_EDGES   1600000
#define N_FEAT    128
#define N_WORKERS 4
#define SCAN_B    1024
#define N_SBLK    ((N_NODES + SCAN_B - 1) / SCAN_B)   // 98

typedef unsigned long long u64;

// Scratch (static device arrays; no allocation).
__device__ unsigned g_deg [2 * N_WORKERS * N_NODES];  // [out | in] raw counts
__device__ float    g_dinv[2 * N_WORKERS * N_NODES];  // [out | in] deg^-1/2 (clipped)
__device__ int      g_is64;
__device__ unsigned g_off [N_WORKERS * N_NODES];      // CSR row offsets (by dst)
__device__ unsigned g_cur [N_WORKERS * N_NODES];      // fill cursors
__device__ unsigned g_bsum[N_WORKERS * N_SBLK];       // scan block sums
__device__ int      g_csr [N_WORKERS * N_EDGES];      // src ids grouped by dst
__device__ __half2  g_f16 [N_WORKERS * N_NODES * (N_FEAT / 2)];  // fp16(feat*dinv_out)

// Packed fp32x2 FMA (Blackwell FFMA2; ptxas never emits this from C++).
#define FMA2(acc, a, b) \
    asm("fma.rn.f32x2 %0, %1, %2, %0;" : "+l"(acc) : "l"(a), "l"(b))

// ---------------------------------------------------------------------------
// int64 vs int32 index detection (indices < 100000 -> odd words zero iff i64).
// ---------------------------------------------------------------------------
__global__ void detect_idx_kernel(const unsigned int* __restrict__ p) {
    __shared__ int any;
    if (threadIdx.x == 0) any = 0;
    __syncthreads();
    if (p[2 * threadIdx.x + 1] != 0u) any = 1;
    __syncthreads();
    if (threadIdx.x == 0) g_is64 = (any == 0) ? 1 : 0;
}

__device__ __forceinline__ int load_idx(const void* p, long long i, int is64) {
    if (is64) return (int)((const long long*)p)[i];
    return ((const int*)p)[i];
}

// ---------------------------------------------------------------------------
// Degree counting (all workers, grid.y = worker).
// ---------------------------------------------------------------------------
__global__ void degree_kernel(const void* __restrict__ src, const void* __restrict__ dst) {
    int is64 = g_is64;
    int w = blockIdx.y;
    long long base = (long long)w * N_EDGES;
    for (int e = blockIdx.x * blockDim.x + threadIdx.x; e < N_EDGES;
         e += gridDim.x * blockDim.x) {
        int s = load_idx(src, base + e, is64);
        int d = load_idx(dst, base + e, is64);
        atomicAdd(&g_deg[w * N_NODES + s], 1u);
        atomicAdd(&g_deg[N_WORKERS * N_NODES + w * N_NODES + d], 1u);
    }
}

__global__ void dinv_kernel() {
    int i = blockIdx.x * blockDim.x + threadIdx.x;
    if (i < 2 * N_WORKERS * N_NODES) {
        float c = (float)g_deg[i];
        g_dinv[i] = rsqrtf(fmaxf(c, 1.0f));
    }
}

// ---------------------------------------------------------------------------
// Convert: feat16[g][f] = fp16(feat[g][f] * outdeg(g)^-1/2). 64 half2 per row.
// ---------------------------------------------------------------------------
__global__ void conv16_kernel(const float* __restrict__ feats) {
    long long i = (long long)blockIdx.x * blockDim.x + threadIdx.x;
    const long long total = (long long)N_WORKERS * N_NODES * (N_FEAT / 2);
    if (i >= total) return;
    int g = (int)(i >> 6);              // global node index (w-major) = dinv_out index
    float sc = g_dinv[g];
    float2 v = ((const float2*)feats)[i];
    g_f16[i] = __floats2half2_rn(v.x * sc, v.y * sc);
}

// ---------------------------------------------------------------------------
// Exclusive scan of in-degrees -> CSR offsets.
// ---------------------------------------------------------------------------
__global__ void scan1_kernel() {
    __shared__ unsigned s[SCAN_B];
    int w = blockIdx.y;
    int i = blockIdx.x * SCAN_B + threadIdx.x;
    unsigned v = (i < N_NODES) ? g_deg[N_WORKERS * N_NODES + w * N_NODES + i] : 0u;
    s[threadIdx.x] = v;
    __syncthreads();
    for (int d = 1; d < SCAN_B; d <<= 1) {
        unsigned t = (threadIdx.x >= d) ? s[threadIdx.x - d] : 0u;
        __syncthreads();
        s[threadIdx.x] += t;
        __syncthreads();
    }
    if (i < N_NODES) g_off[w * N_NODES + i] = s[threadIdx.x] - v;  // exclusive
    if (threadIdx.x == SCAN_B - 1) g_bsum[w * N_SBLK + blockIdx.x] = s[threadIdx.x];
}

__global__ void scan2_kernel() {
    int w = blockIdx.x;
    if (threadIdx.x != 0) return;
    unsigned acc = 0;
    for (int b = 0; b < N_SBLK; b++) {
        unsigned t = g_bsum[w * N_SBLK + b];
        g_bsum[w * N_SBLK + b] = acc;
        acc += t;
    }
}

__global__ void scan3_kernel() {
    int w = blockIdx.y;
    int i = blockIdx.x * 256 + threadIdx.x;
    if (i < N_NODES) g_off[w * N_NODES + i] += g_bsum[w * N_SBLK + i / SCAN_B];
}

// ---------------------------------------------------------------------------
// CSR fill: bucket src ids by dst. Small 4B atomics only.
// ---------------------------------------------------------------------------
__global__ void fill_kernel(const void* __restrict__ src, const void* __restrict__ dst) {
    int is64 = g_is64;
    int w = blockIdx.y;
    long long base = (long long)w * N_EDGES;
    for (int e = blockIdx.x * blockDim.x + threadIdx.x; e < N_EDGES;
         e += gridDim.x * blockDim.x) {
        int s = load_idx(src, base + e, is64);
        int d = load_idx(dst, base + e, is64);
        unsigned pos = g_off[w * N_NODES + d] + atomicAdd(&g_cur[w * N_NODES + d], 1u);
        g_csr[base + pos] = s;
    }
}

// ---------------------------------------------------------------------------
// Fused gather(fp16) + scale + FFMA2 GEMM + bias. One launch, grid (1563, 4).
//   Phase 1: W -> smem, INTERLEAVED as (W[2f][c], W[2f+1][c]) f32-pairs
//   Phase 2: each warp sums 8 nodes' fp16 rows (f32 accum) -> smem As
//   Phase 3: even/odd-split register-tiled GEMM on fma.rn.f32x2
// ---------------------------------------------------------------------------
__global__ void __launch_bounds__(256)
fused_kernel(const float* __restrict__ weight,
             const float* __restrict__ bias,
             float* __restrict__ out) {
    extern __shared__ float sm[];
    float* Wi = sm;                    // 128*128 (interleaved f-pairs)
    float* As = sm + N_FEAT * N_FEAT;  // 64*128
    u64* Wu = (u64*)Wi;
    int t = threadIdx.x;
    int lane = t & 31;
    int warp = t >> 5;
    int w = blockIdx.y;

    // Phase 1: Wu[fp*128 + c] = (W[2fp][c], W[2fp+1][c])
    for (int i = t; i < (N_FEAT / 2) * N_FEAT; i += 256) {
        int fp = i >> 7;
        int c  = i & 127;
        float w0 = weight[(2 * fp)     * N_FEAT + c];
        float w1 = weight[(2 * fp + 1) * N_FEAT + c];
        u64 pk;
        asm("mov.b64 %0, {%1, %2};" : "=l"(pk) : "f"(w0), "f"(w1));
        Wu[i] = pk;
    }

    int n0 = blockIdx.x * 64;
    const __half2*  fw      = g_f16 + (long long)w * N_NODES * (N_FEAT / 2);
    const int*      csrw    = g_csr + (long long)w * N_EDGES;
    const float*    dinv_in = g_dinv + N_WORKERS * N_NODES + w * N_NODES;
    const unsigned* offw    = g_off + w * N_NODES;
    const unsigned* degw    = g_deg + N_WORKERS * N_NODES + w * N_NODES;

    // Phase 2: gather. Warp g handles nodes n0+g*8 .. n0+g*8+7.
    // Lane handles feats [4*lane, 4*lane+4) = 2 half2 = one 8B load per edge.
#pragma unroll
    for (int i = 0; i < 8; i++) {
        int node = n0 + warp * 8 + i;
        float4 acc = make_float4(0.f, 0.f, 0.f, 0.f);
        if (node < N_NODES) {
            unsigned st  = offw[node];
            unsigned deg = degw[node];
            const int* ep = csrw + st;
#pragma unroll 8
            for (unsigned j = 0; j < deg; j++) {
                int s = ep[j];                          // broadcast 4B
                uint2 u = *(const uint2*)(fw + (long long)s * (N_FEAT / 2) + lane * 2);
                float2 f01 = __half22float2(*(const __half2*)&u.x);
                float2 f23 = __half22float2(*(const __half2*)&u.y);
                acc.x += f01.x; acc.y += f01.y;
                acc.z += f23.x; acc.w += f23.y;
            }
            float si = dinv_in[node];
            acc.x *= si; acc.y *= si; acc.z *= si; acc.w *= si;
        }
        *(float4*)&As[(warp * 8 + i) * N_FEAT + lane * 4] = acc;
    }
    __syncthreads();

    // Phase 3: GEMM. tx in [0,32): cols {2tx,2tx+1,64+2tx,64+2tx+1};
    //          ty in [0,8): rows ty*8 .. ty*8+7. Even/odd K split in f32x2.
    int tx = t & 31;
    int ty = t >> 5;
    u64 acc[8][4];
#pragma unroll
    for (int k = 0; k < 8; k++)
#pragma unroll
        for (int j = 0; j < 4; j++) acc[k][j] = 0ull;

    for (int fp = 0; fp < N_FEAT / 2; fp += 2) {
        ulonglong2 w0a = *(const ulonglong2*)&Wu[fp * 128 + 2 * tx];
        ulonglong2 w0b = *(const ulonglong2*)&Wu[fp * 128 + 64 + 2 * tx];
        ulonglong2 w1a = *(const ulonglong2*)&Wu[(fp + 1) * 128 + 2 * tx];
        ulonglong2 w1b = *(const ulonglong2*)&Wu[(fp + 1) * 128 + 64 + 2 * tx];
#pragma unroll
        for (int k = 0; k < 8; k++) {
            ulonglong2 a = *(const ulonglong2*)&As[(ty * 8 + k) * N_FEAT + 2 * fp];
            FMA2(acc[k][0], a.x, w0a.x);
            FMA2(acc[k][1], a.x, w0a.y);
            FMA2(acc[k][2], a.x, w0b.x);
            FMA2(acc[k][3], a.x, w0b.y);
            FMA2(acc[k][0], a.y, w1a.x);
            FMA2(acc[k][1], a.y, w1a.y);
            FMA2(acc[k][2], a.y, w1b.x);
            FMA2(acc[k][3], a.y, w1b.y);
        }
    }

    float2 bA = *(const float2*)&bias[2 * tx];
    float2 bB = *(const float2*)&bias[64 + 2 * tx];
    float* outw = out + (long long)w * N_NODES * N_FEAT;
#pragma unroll
    for (int k = 0; k < 8; k++) {
        int row = n0 + ty * 8 + k;
        if (row < N_NODES) {
            float lo, hi;
            float2 rA, rB;
            asm("mov.b64 {%0, %1}, %2;" : "=f"(lo), "=f"(hi) : "l"(acc[k][0]));
            rA.x = lo + hi + bA.x;
            asm("mov.b64 {%0, %1}, %2;" : "=f"(lo), "=f"(hi) : "l"(acc[k][1]));
            rA.y = lo + hi + bA.y;
            asm("mov.b64 {%0, %1}, %2;" : "=f"(lo), "=f"(hi) : "l"(acc[k][2]));
            rB.x = lo + hi + bB.x;
            asm("mov.b64 {%0, %1}, %2;" : "=f"(lo), "=f"(hi) : "l"(acc[k][3]));
            rB.y = lo + hi + bB.y;
            *(float2*)(outw + (long long)row * N_FEAT + 2 * tx)      = rA;
            *(float2*)(outw + (long long)row * N_FEAT + 64 + 2 * tx) = rB;
        }
    }
}

// ---------------------------------------------------------------------------
extern "C" void kernel_launch(void* const* d_in, const int* in_sizes, int n_in,
                              void* d_out, int out_size) {
    const float* feats  = (const float*)d_in[0];
    const float* weight = (const float*)d_in[1];
    const float* bias   = (const float*)d_in[2];
    const void*  src    = d_in[3];
    const void*  dst    = d_in[4];
    float* out = (float*)d_out;

    void* p = nullptr;
    cudaGetSymbolAddress(&p, g_deg);
    cudaMemsetAsync(p, 0, sizeof(unsigned) * 2 * N_WORKERS * N_NODES);
    cudaGetSymbolAddress(&p, g_cur);
    cudaMemsetAsync(p, 0, sizeof(unsigned) * N_WORKERS * N_NODES);

    detect_idx_kernel<<<1, 256>>>((const unsigned int*)src);

    dim3 dgrid(2048, N_WORKERS);
    degree_kernel<<<dgrid, 256>>>(src, dst);
    dinv_kernel<<<(2 * N_WORKERS * N_NODES + 255) / 256, 256>>>();

    // fp16 cache of outdeg-scaled feats (independent of scan/fill; overlaps them)
    const long long nconv = (long long)N_WORKERS * N_NODES * (N_FEAT / 2);
    conv16_kernel<<<(int)((nconv + 255) / 256), 256>>>(feats);

    dim3 sgrid1(N_SBLK, N_WORKERS);
    scan1_kernel<<<sgrid1, SCAN_B>>>();
    scan2_kernel<<<N_WORKERS, 32>>>();
    dim3 sgrid3((N_NODES + 255) / 256, N_WORKERS);
    scan3_kernel<<<sgrid3, 256>>>();

    fill_kernel<<<dgrid, 256>>>(src, dst);

    const int smem = (N_FEAT * N_FEAT + 64 * N_FEAT) * sizeof(float);  // 96 KB
    cudaFuncSetAttribute(fused_kernel, cudaFuncAttributeMaxDynamicSharedMemorySize, smem);
    dim3 fgrid((N_NODES + 63) / 64, N_WORKERS);  // (1563, 4)
    fused_kernel<<<fgrid, 256, smem>>>(weight, bias, out);
}

// round 11
// speedup vs baseline: 2.8909x; 1.3719x over previous
#include <cuda_runtime.h>
#include <cuda_fp16.h>

#define N_NODES   100000
#define N_EDGES   1600000
#define N_FEAT    128
#define N_WORKERS 4
#define N_ROWS    (N_WORKERS * N_NODES)               // 400000 flattened rows
#define SCAN_B    1024
#define N_SBLK    ((N_NODES + SCAN_B - 1) / SCAN_B)   // 98

typedef unsigned long long u64;

// Scratch (static device arrays; no allocation).
__device__ unsigned g_deg [2 * N_ROWS];               // [out | in] raw counts
__device__ float    g_dinv[2 * N_ROWS];               // [out | in] deg^-1/2 (clipped)
__device__ int      g_is64;
__device__ unsigned g_off [N_ROWS];                   // CSR row offsets (by dst)
__device__ unsigned g_cur [N_ROWS];                   // fill cursors
__device__ unsigned g_bsum[N_WORKERS * N_SBLK];       // scan block sums
__device__ int      g_csr [N_WORKERS * N_EDGES];      // src ids grouped by dst
__device__ __half2  g_x16 [(long long)N_ROWS * (N_FEAT / 2)];  // fp16((feat*dout)@W)

// Packed fp32x2 FMA (Blackwell FFMA2; ptxas never emits this from C++).
#define FMA2(acc, a, b) \
    asm("fma.rn.f32x2 %0, %1, %2, %0;" : "+l"(acc) : "l"(a), "l"(b))

// ---------------------------------------------------------------------------
// int64 vs int32 index detection (indices < 100000 -> odd words zero iff i64).
// ---------------------------------------------------------------------------
__global__ void detect_idx_kernel(const unsigned int* __restrict__ p) {
    __shared__ int any;
    if (threadIdx.x == 0) any = 0;
    __syncthreads();
    if (p[2 * threadIdx.x + 1] != 0u) any = 1;
    __syncthreads();
    if (threadIdx.x == 0) g_is64 = (any == 0) ? 1 : 0;
}

__device__ __forceinline__ int load_idx(const void* p, long long i, int is64) {
    if (is64) return (int)((const long long*)p)[i];
    return ((const int*)p)[i];
}

// ---------------------------------------------------------------------------
// Degree counting (all workers, grid.y = worker).
// ---------------------------------------------------------------------------
__global__ void degree_kernel(const void* __restrict__ src, const void* __restrict__ dst) {
    int is64 = g_is64;
    int w = blockIdx.y;
    long long base = (long long)w * N_EDGES;
    for (int e = blockIdx.x * blockDim.x + threadIdx.x; e < N_EDGES;
         e += gridDim.x * blockDim.x) {
        int s = load_idx(src, base + e, is64);
        int d = load_idx(dst, base + e, is64);
        atomicAdd(&g_deg[w * N_NODES + s], 1u);
        atomicAdd(&g_deg[N_ROWS + w * N_NODES + d], 1u);
    }
}

__global__ void dinv_kernel() {
    int i = blockIdx.x * blockDim.x + threadIdx.x;
    if (i < 2 * N_ROWS) {
        float c = (float)g_deg[i];
        g_dinv[i] = rsqrtf(fmaxf(c, 1.0f));
    }
}

// ---------------------------------------------------------------------------
// Dense GEMM: X16[r] = fp16( (feat[r] * outdeg(r)^-1/2) @ W ), r in [0,400000).
//   Phase 1: W -> smem INTERLEAVED as (W[2f][c], W[2f+1][c]) f32-pairs
//   Phase 2: 64 feat rows -> smem, scaled by dinv_out
//   Phase 3: even/odd-K-split register-tiled FFMA2 GEMM -> fp16 out
// FFMA2 semantics: acc[k][j] = (even-K partial, odd-K partial) of ONE column.
//   acc[k][0] -> col 2tx      acc[k][1] -> col 2tx+1
//   acc[k][2] -> col 64+2tx   acc[k][3] -> col 64+2tx+1
// Column value = acc.lo + acc.hi  (merge WITHIN an accumulator).
// Output layout: half2 index h in [0,64) holds cols (2h, 2h+1).
// ---------------------------------------------------------------------------
__global__ void __launch_bounds__(256)
gemm16_kernel(const float* __restrict__ feats,
              const float* __restrict__ weight) {
    extern __shared__ float sm[];
    float* Wi = sm;                    // 128*128 interleaved pairs (64 KB)
    float* As = sm + N_FEAT * N_FEAT;  // 64*128 (32 KB)
    u64* Wu = (u64*)Wi;
    int t = threadIdx.x;

    for (int i = t; i < (N_FEAT / 2) * N_FEAT; i += 256) {
        int fp = i >> 7;
        int c  = i & 127;
        float w0 = weight[(2 * fp)     * N_FEAT + c];
        float w1 = weight[(2 * fp + 1) * N_FEAT + c];
        u64 pk;
        asm("mov.b64 %0, {%1, %2};" : "=l"(pk) : "f"(w0), "f"(w1));
        Wu[i] = pk;
    }

    long long r0 = (long long)blockIdx.x * 64;

    // 64 rows of feats, scaled by outdeg^-1/2 (flattened row index == dinv_out idx)
    for (int i = t; i < 64 * (N_FEAT / 4); i += 256) {
        int row = i >> 5;  // 32 float4 per row
        float sc = g_dinv[r0 + row];
        float4 v = ((const float4*)(feats + r0 * N_FEAT))[i];
        v.x *= sc; v.y *= sc; v.z *= sc; v.w *= sc;
        *(float4*)&As[i * 4] = v;
    }
    __syncthreads();

    int tx = t & 31;
    int ty = t >> 5;
    u64 acc[8][4];
#pragma unroll
    for (int k = 0; k < 8; k++)
#pragma unroll
        for (int j = 0; j < 4; j++) acc[k][j] = 0ull;

    for (int fp = 0; fp < N_FEAT / 2; fp += 2) {
        ulonglong2 w0a = *(const ulonglong2*)&Wu[fp * 128 + 2 * tx];
        ulonglong2 w0b = *(const ulonglong2*)&Wu[fp * 128 + 64 + 2 * tx];
        ulonglong2 w1a = *(const ulonglong2*)&Wu[(fp + 1) * 128 + 2 * tx];
        ulonglong2 w1b = *(const ulonglong2*)&Wu[(fp + 1) * 128 + 64 + 2 * tx];
#pragma unroll
        for (int k = 0; k < 8; k++) {
            ulonglong2 a = *(const ulonglong2*)&As[(ty * 8 + k) * N_FEAT + 2 * fp];
            FMA2(acc[k][0], a.x, w0a.x);
            FMA2(acc[k][1], a.x, w0a.y);
            FMA2(acc[k][2], a.x, w0b.x);
            FMA2(acc[k][3], a.x, w0b.y);
            FMA2(acc[k][0], a.y, w1a.x);
            FMA2(acc[k][1], a.y, w1a.y);
            FMA2(acc[k][2], a.y, w1b.x);
            FMA2(acc[k][3], a.y, w1b.y);
        }
    }

    __half2* xw = g_x16;
#pragma unroll
    for (int k = 0; k < 8; k++) {
        long long row = r0 + ty * 8 + k;
        float l0, h0, l1, h1;
        // col 2tx = acc[k][0].lo + acc[k][0].hi; col 2tx+1 = acc[k][1].lo + .hi
        asm("mov.b64 {%0, %1}, %2;" : "=f"(l0), "=f"(h0) : "l"(acc[k][0]));
        asm("mov.b64 {%0, %1}, %2;" : "=f"(l1), "=f"(h1) : "l"(acc[k][1]));
        __half2 hA = __floats2half2_rn(l0 + h0, l1 + h1);
        asm("mov.b64 {%0, %1}, %2;" : "=f"(l0), "=f"(h0) : "l"(acc[k][2]));
        asm("mov.b64 {%0, %1}, %2;" : "=f"(l1), "=f"(h1) : "l"(acc[k][3]));
        __half2 hB = __floats2half2_rn(l0 + h0, l1 + h1);
        xw[row * 64 + tx]      = hA;   // h = tx    -> cols (2tx, 2tx+1)
        xw[row * 64 + 32 + tx] = hB;   // h = 32+tx -> cols (64+2tx, 64+2tx+1)
    }
}

// ---------------------------------------------------------------------------
// Exclusive scan of in-degrees -> CSR offsets.
// ---------------------------------------------------------------------------
__global__ void scan1_kernel() {
    __shared__ unsigned s[SCAN_B];
    int w = blockIdx.y;
    int i = blockIdx.x * SCAN_B + threadIdx.x;
    unsigned v = (i < N_NODES) ? g_deg[N_ROWS + w * N_NODES + i] : 0u;
    s[threadIdx.x] = v;
    __syncthreads();
    for (int d = 1; d < SCAN_B; d <<= 1) {
        unsigned t = (threadIdx.x >= d) ? s[threadIdx.x - d] : 0u;
        __syncthreads();
        s[threadIdx.x] += t;
        __syncthreads();
    }
    if (i < N_NODES) g_off[w * N_NODES + i] = s[threadIdx.x] - v;  // exclusive
    if (threadIdx.x == SCAN_B - 1) g_bsum[w * N_SBLK + blockIdx.x] = s[threadIdx.x];
}

__global__ void scan2_kernel() {
    int w = blockIdx.x;
    if (threadIdx.x != 0) return;
    unsigned acc = 0;
    for (int b = 0; b < N_SBLK; b++) {
        unsigned t = g_bsum[w * N_SBLK + b];
        g_bsum[w * N_SBLK + b] = acc;
        acc += t;
    }
}

__global__ void scan3_kernel() {
    int w = blockIdx.y;
    int i = blockIdx.x * 256 + threadIdx.x;
    if (i < N_NODES) g_off[w * N_NODES + i] += g_bsum[w * N_SBLK + i / SCAN_B];
}

// ---------------------------------------------------------------------------
// CSR fill: bucket src ids by dst. Small 4B atomics only.
// ---------------------------------------------------------------------------
__global__ void fill_kernel(const void* __restrict__ src, const void* __restrict__ dst) {
    int is64 = g_is64;
    int w = blockIdx.y;
    long long base = (long long)w * N_EDGES;
    for (int e = blockIdx.x * blockDim.x + threadIdx.x; e < N_EDGES;
         e += gridDim.x * blockDim.x) {
        int s = load_idx(src, base + e, is64);
        int d = load_idx(dst, base + e, is64);
        unsigned pos = g_off[w * N_NODES + d] + atomicAdd(&g_cur[w * N_NODES + d], 1u);
        g_csr[base + pos] = s;
    }
}

// ---------------------------------------------------------------------------
// Gather: out[r] = indeg(r)^-1/2 * sum_{s in CSR[r]} X16[s] + bias.
// Warp per row, zero smem -> full occupancy; pure L2-BW bound.
// Lane reads half2 pair {2*lane, 2*lane+1} = cols [4*lane, 4*lane+4).
// ---------------------------------------------------------------------------
__global__ void __launch_bounds__(256)
gather_kernel(const float* __restrict__ bias, float* __restrict__ out) {
    int lane = threadIdx.x & 31;
    long long r = (long long)((blockIdx.x * blockDim.x + threadIdx.x) >> 5);
    if (r >= N_ROWS) return;
    int w = (int)(r / N_NODES);

    unsigned st  = g_off[r];
    unsigned deg = g_deg[N_ROWS + r];
    const int* ep = g_csr + (long long)w * N_EDGES + st;
    const __half2* xw = g_x16 + (long long)w * N_NODES * (N_FEAT / 2);

    float4 acc = make_float4(0.f, 0.f, 0.f, 0.f);
#pragma unroll 4
    for (unsigned j = 0; j < deg; j++) {
        int s = ep[j];                                  // broadcast 4B
        uint2 u = *(const uint2*)(xw + (long long)s * (N_FEAT / 2) + lane * 2);
        float2 f01 = __half22float2(*(const __half2*)&u.x);
        float2 f23 = __half22float2(*(const __half2*)&u.y);
        acc.x += f01.x; acc.y += f01.y;
        acc.z += f23.x; acc.w += f23.y;
    }
    float si = g_dinv[N_ROWS + r];
    float4 bv = *((const float4*)bias + lane);
    float4 o;
    o.x = acc.x * si + bv.x;
    o.y = acc.y * si + bv.y;
    o.z = acc.z * si + bv.z;
    o.w = acc.w * si + bv.w;
    *((float4*)(out + r * N_FEAT) + lane) = o;
}

// ---------------------------------------------------------------------------
extern "C" void kernel_launch(void* const* d_in, const int* in_sizes, int n_in,
                              void* d_out, int out_size) {
    const float* feats  = (const float*)d_in[0];
    const float* weight = (const float*)d_in[1];
    const float* bias   = (const float*)d_in[2];
    const void*  src    = d_in[3];
    const void*  dst    = d_in[4];
    float* out = (float*)d_out;

    void* p = nullptr;
    cudaGetSymbolAddress(&p, g_deg);
    cudaMemsetAsync(p, 0, sizeof(unsigned) * 2 * N_ROWS);
    cudaGetSymbolAddress(&p, g_cur);
    cudaMemsetAsync(p, 0, sizeof(unsigned) * N_ROWS);

    detect_idx_kernel<<<1, 256>>>((const unsigned int*)src);

    dim3 dgrid(2048, N_WORKERS);
    degree_kernel<<<dgrid, 256>>>(src, dst);
    dinv_kernel<<<(2 * N_ROWS + 255) / 256, 256>>>();

    // Dense GEMM: depends only on dinv (out-degrees).
    const int smem = (N_FEAT * N_FEAT + 64 * N_FEAT) * sizeof(float);  // 96 KB
    cudaFuncSetAttribute(gemm16_kernel, cudaFuncAttributeMaxDynamicSharedMemorySize, smem);
    gemm16_kernel<<<N_ROWS / 64, 256, smem>>>(feats, weight);

    dim3 sgrid1(N_SBLK, N_WORKERS);
    scan1_kernel<<<sgrid1, SCAN_B>>>();
    scan2_kernel<<<N_WORKERS, 32>>>();
    dim3 sgrid3((N_NODES + 255) / 256, N_WORKERS);
    scan3_kernel<<<sgrid3, 256>>>();

    fill_kernel<<<dgrid, 256>>>(src, dst);

    gather_kernel<<<(N_ROWS * 32 + 255) / 256, 256>>>(bias, out);
}

// round 13
// speedup vs baseline: 4.1494x; 1.4353x over previous
#include <cuda_runtime.h>
#include <cuda_fp16.h>
#include <cstdint>

#define N_NODES   100000
#define N_EDGES   1600000
#define N_FEAT    128
#define N_WORKERS 4
#define N_ROWS    (N_WORKERS * N_NODES)               // 400000 flattened rows
#define SCAN_B    1024
#define N_SBLK    ((N_NODES + SCAN_B - 1) / SCAN_B)   // 98
#define APAD      136                                 // padded half-stride (conflict-free)
#define SPAD      68                                  // padded u32-stride for staging

typedef unsigned long long u64;

// Scratch (static device arrays; no allocation).
__device__ unsigned g_deg [2 * N_ROWS];               // [out | in] raw counts
__device__ float    g_dinv[2 * N_ROWS];               // [out | in] deg^-1/2 (clipped)
__device__ int      g_is64;
__device__ unsigned g_off [N_ROWS];                   // CSR row offsets (by dst)
__device__ unsigned g_cur [N_ROWS];                   // fill cursors
__device__ unsigned g_bsum[N_WORKERS * N_SBLK];       // scan block sums
__device__ int      g_csr [N_WORKERS * N_EDGES];      // src ids grouped by dst
__device__ __align__(16) __half2 g_x16[(long long)N_ROWS * (N_FEAT / 2)];

// ---------------------------------------------------------------------------
// int64 vs int32 index detection (indices < 100000 -> odd words zero iff i64).
// ---------------------------------------------------------------------------
__global__ void detect_idx_kernel(const unsigned int* __restrict__ p) {
    __shared__ int any;
    if (threadIdx.x == 0) any = 0;
    __syncthreads();
    if (p[2 * threadIdx.x + 1] != 0u) any = 1;
    __syncthreads();
    if (threadIdx.x == 0) g_is64 = (any == 0) ? 1 : 0;
}

__device__ __forceinline__ int load_idx(const void* p, long long i, int is64) {
    if (is64) return (int)((const long long*)p)[i];
    return ((const int*)p)[i];
}

// ---------------------------------------------------------------------------
// Degree counting (all workers, grid.y = worker).
// ---------------------------------------------------------------------------
__global__ void degree_kernel(const void* __restrict__ src, const void* __restrict__ dst) {
    int is64 = g_is64;
    int w = blockIdx.y;
    long long base = (long long)w * N_EDGES;
    for (int e = blockIdx.x * blockDim.x + threadIdx.x; e < N_EDGES;
         e += gridDim.x * blockDim.x) {
        int s = load_idx(src, base + e, is64);
        int d = load_idx(dst, base + e, is64);
        atomicAdd(&g_deg[w * N_NODES + s], 1u);
        atomicAdd(&g_deg[N_ROWS + w * N_NODES + d], 1u);
    }
}

__global__ void dinv_kernel() {
    int i = blockIdx.x * blockDim.x + threadIdx.x;
    if (i < 2 * N_ROWS) {
        float c = (float)g_deg[i];
        g_dinv[i] = rsqrtf(fmaxf(c, 1.0f));
    }
}

// ---------------------------------------------------------------------------
// HMMA GEMM: X16[r] = fp16( (feat[r]*outdeg^-1/2) @ W ), tile M=128,N=128,K=128.
// mma.sync.m16n8k16.row.col f32.f16.f16.f32. 8 warps; warp = 16-row strip.
// Fragment mapping (gid = lane>>2, tig = lane&3):
//   A: a0=A[g][2t..+1]  a1=A[g+8][2t..]  a2=A[g][2t+8..]  a3=A[g+8][2t+8..]
//   B: b0=B[2t..+1][g]  b1=B[2t+8..][g]   (B col-major = Wt[n][k] row-major)
//   C: c0,c1=C[g][2t..+1]  c2,c3=C[g+8][2t..+1]
// Pad-136 rows: row base bank = 4*row mod 32, lanes add 0..3 -> all 32 banks.
// ---------------------------------------------------------------------------
#define SMEM_TOT (2 * 128 * APAD * 2)   // 69632 B

__global__ void __launch_bounds__(256)
gemm_mma_kernel(const float* __restrict__ feats, const float* __restrict__ weight) {
    extern __shared__ __half smh[];
    __half* As = smh;                  // 128 x APAD
    __half* Wt = smh + 128 * APAD;     // 128 x APAD;  Wt[n][k] = W[k][n]
    int t = threadIdx.x, lane = t & 31, wid = t >> 5;
    int gid = lane >> 2, tig = lane & 3;
    long long r0 = (long long)blockIdx.x * 128;

    // A tile: 128 rows x 128 f32 -> fp16 scaled by outdeg^-1/2
    {
        const float4* src = (const float4*)(feats + r0 * N_FEAT);
#pragma unroll 4
        for (int i = t; i < 128 * 32; i += 256) {
            int row = i >> 5, c4 = i & 31;
            float sc = g_dinv[r0 + row];
            float4 v = src[i];
            __half2 h0 = __floats2half2_rn(v.x * sc, v.y * sc);
            __half2 h1 = __floats2half2_rn(v.z * sc, v.w * sc);
            *(uint2*)(As + row * APAD + c4 * 4) =
                make_uint2(*(uint32_t*)&h0, *(uint32_t*)&h1);
        }
    }
    // W^T tile: coalesced read of W[f][c], transposed 2B store
#pragma unroll 4
    for (int i = t; i < 128 * 128; i += 256) {
        int f = i >> 7, c = i & 127;
        Wt[c * APAD + f] = __float2half_rn(weight[i]);
    }
    __syncthreads();

    float c[16][4];
#pragma unroll
    for (int j = 0; j < 16; j++)
#pragma unroll
        for (int i = 0; i < 4; i++) c[j][i] = 0.0f;

    int m0 = wid * 16;
    const __half* ar0 = As + (m0 + gid) * APAD + 2 * tig;
    const __half* ar1 = ar0 + 8 * APAD;

#pragma unroll
    for (int ks = 0; ks < 8; ks++) {
        int k0 = ks * 16;
        uint32_t a0 = *(const uint32_t*)(ar0 + k0);
        uint32_t a1 = *(const uint32_t*)(ar1 + k0);
        uint32_t a2 = *(const uint32_t*)(ar0 + k0 + 8);
        uint32_t a3 = *(const uint32_t*)(ar1 + k0 + 8);
        const __half* bp = Wt + gid * APAD + k0 + 2 * tig;
#pragma unroll
        for (int j = 0; j < 16; j++) {
            uint32_t b0 = *(const uint32_t*)(bp);
            uint32_t b1 = *(const uint32_t*)(bp + 8);
            bp += 8 * APAD;
            asm volatile(
                "mma.sync.aligned.m16n8k16.row.col.f32.f16.f16.f32 "
                "{%0,%1,%2,%3}, {%4,%5,%6,%7}, {%8,%9}, {%0,%1,%2,%3};"
                : "+f"(c[j][0]), "+f"(c[j][1]), "+f"(c[j][2]), "+f"(c[j][3])
                : "r"(a0), "r"(a1), "r"(a2), "r"(a3), "r"(b0), "r"(b1));
        }
    }

    // Epilogue: frags -> padded staging (reuses A region) -> coalesced uint4 STG
    __syncthreads();
    uint32_t* stg = (uint32_t*)As;     // 128 x SPAD u32 = 34816 B (= A region)
#pragma unroll
    for (int j = 0; j < 16; j++) {
        __half2 h0 = __floats2half2_rn(c[j][0], c[j][1]);
        __half2 h1 = __floats2half2_rn(c[j][2], c[j][3]);
        stg[(m0 + gid)     * SPAD + 4 * j + tig] = *(uint32_t*)&h0;
        stg[(m0 + gid + 8) * SPAD + 4 * j + tig] = *(uint32_t*)&h1;
    }
    __syncthreads();
    uint4* outp = (uint4*)(g_x16 + r0 * (N_FEAT / 2));
#pragma unroll
    for (int i = 0; i < 8; i++) {
        int idx = t + i * 256;         // 2048 uint4 = 128 rows x 16
        int rr = idx >> 4, j4 = idx & 15;
        const uint32_t* p = stg + rr * SPAD + j4 * 4;
        outp[idx] = make_uint4(p[0], p[1], p[2], p[3]);
    }
}

// ---------------------------------------------------------------------------
// Exclusive scan of in-degrees -> CSR offsets.
// ---------------------------------------------------------------------------
__global__ void scan1_kernel() {
    __shared__ unsigned s[SCAN_B];
    int w = blockIdx.y;
    int i = blockIdx.x * SCAN_B + threadIdx.x;
    unsigned v = (i < N_NODES) ? g_deg[N_ROWS + w * N_NODES + i] : 0u;
    s[threadIdx.x] = v;
    __syncthreads();
    for (int d = 1; d < SCAN_B; d <<= 1) {
        unsigned t = (threadIdx.x >= d) ? s[threadIdx.x - d] : 0u;
        __syncthreads();
        s[threadIdx.x] += t;
        __syncthreads();
    }
    if (i < N_NODES) g_off[w * N_NODES + i] = s[threadIdx.x] - v;  // exclusive
    if (threadIdx.x == SCAN_B - 1) g_bsum[w * N_SBLK + blockIdx.x] = s[threadIdx.x];
}

__global__ void scan2_kernel() {
    int w = blockIdx.x;
    if (threadIdx.x != 0) return;
    unsigned acc = 0;
    for (int b = 0; b < N_SBLK; b++) {
        unsigned t = g_bsum[w * N_SBLK + b];
        g_bsum[w * N_SBLK + b] = acc;
        acc += t;
    }
}

__global__ void scan3_kernel() {
    int w = blockIdx.y;
    int i = blockIdx.x * 256 + threadIdx.x;
    if (i < N_NODES) g_off[w * N_NODES + i] += g_bsum[w * N_SBLK + i / SCAN_B];
}

// ---------------------------------------------------------------------------
// CSR fill: bucket src ids by dst. Small 4B atomics only.
// ---------------------------------------------------------------------------
__global__ void fill_kernel(const void* __restrict__ src, const void* __restrict__ dst) {
    int is64 = g_is64;
    int w = blockIdx.y;
    long long base = (long long)w * N_EDGES;
    for (int e = blockIdx.x * blockDim.x + threadIdx.x; e < N_EDGES;
         e += gridDim.x * blockDim.x) {
        int s = load_idx(src, base + e, is64);
        int d = load_idx(dst, base + e, is64);
        unsigned pos = g_off[w * N_NODES + d] + atomicAdd(&g_cur[w * N_NODES + d], 1u);
        g_csr[base + pos] = s;
    }
}

// ---------------------------------------------------------------------------
// Gather: out[r] = indeg(r)^-1/2 * sum_{s in CSR[r]} X16[s] + bias.
// Warp per row, zero smem -> full occupancy; pure L2-BW bound.
// ---------------------------------------------------------------------------
__global__ void __launch_bounds__(256)
gather_kernel(const float* __restrict__ bias, float* __restrict__ out) {
    int lane = threadIdx.x & 31;
    long long r = (long long)((blockIdx.x * blockDim.x + threadIdx.x) >> 5);
    if (r >= N_ROWS) return;
    int w = (int)(r / N_NODES);

    unsigned st  = g_off[r];
    unsigned deg = g_deg[N_ROWS + r];
    const int* ep = g_csr + (long long)w * N_EDGES + st;
    const __half2* xw = g_x16 + (long long)w * N_NODES * (N_FEAT / 2);

    float4 acc = make_float4(0.f, 0.f, 0.f, 0.f);
#pragma unroll 4
    for (unsigned j = 0; j < deg; j++) {
        int s = ep[j];                                  // broadcast 4B
        uint2 u = *(const uint2*)(xw + (long long)s * (N_FEAT / 2) + lane * 2);
        float2 f01 = __half22float2(*(const __half2*)&u.x);
        float2 f23 = __half22float2(*(const __half2*)&u.y);
        acc.x += f01.x; acc.y += f01.y;
        acc.z += f23.x; acc.w += f23.y;
    }
    float si = g_dinv[N_ROWS + r];
    float4 bv = *((const float4*)bias + lane);
    float4 o;
    o.x = acc.x * si + bv.x;
    o.y = acc.y * si + bv.y;
    o.z = acc.z * si + bv.z;
    o.w = acc.w * si + bv.w;
    *((float4*)(out + r * N_FEAT) + lane) = o;
}

// ---------------------------------------------------------------------------
extern "C" void kernel_launch(void* const* d_in, const int* in_sizes, int n_in,
                              void* d_out, int out_size) {
    const float* feats  = (const float*)d_in[0];
    const float* weight = (const float*)d_in[1];
    const float* bias   = (const float*)d_in[2];
    const void*  src    = d_in[3];
    const void*  dst    = d_in[4];
    float* out = (float*)d_out;

    void* p = nullptr;
    cudaGetSymbolAddress(&p, g_deg);
    cudaMemsetAsync(p, 0, sizeof(unsigned) * 2 * N_ROWS);
    cudaGetSymbolAddress(&p, g_cur);
    cudaMemsetAsync(p, 0, sizeof(unsigned) * N_ROWS);

    detect_idx_kernel<<<1, 256>>>((const unsigned int*)src);

    dim3 dgrid(2048, N_WORKERS);
    degree_kernel<<<dgrid, 256>>>(src, dst);
    dinv_kernel<<<(2 * N_ROWS + 255) / 256, 256>>>();

    // HMMA GEMM: depends only on dinv (out-degrees).
    cudaFuncSetAttribute(gemm_mma_kernel, cudaFuncAttributeMaxDynamicSharedMemorySize,
                         SMEM_TOT);
    gemm_mma_kernel<<<N_ROWS / 128, 256, SMEM_TOT>>>(feats, weight);

    dim3 sgrid1(N_SBLK, N_WORKERS);
    scan1_kernel<<<sgrid1, SCAN_B>>>();
    scan2_kernel<<<N_WORKERS, 32>>>();
    dim3 sgrid3((N_NODES + 255) / 256, N_WORKERS);
    scan3_kernel<<<sgrid3, 256>>>();

    fill_kernel<<<dgrid, 256>>>(src, dst);

    gather_kernel<<<(N_ROWS * 32 + 255) / 256, 256>>>(bias, out);
}